// round 1
// baseline (speedup 1.0000x reference)
#include <cuda_runtime.h>

// F[b, s, q*96+v] = scale * K[b,s,3,q] * u[b,s,v]
//   u[b,s,v] = sum_i t[b,s,i] * W3[i,v]
//   t[b,s,i] = sum_k Q[b,s,3,k] * V[b,s,k,i]
// where Q,K,V are the raw (B,96,96,96) arrays, W3 = depth_weights[uidx].

#define S96 96

__global__ __launch_bounds__(S96) void mma73_kernel(
    const float* __restrict__ Q,
    const float* __restrict__ K,
    const float* __restrict__ V,
    const float* __restrict__ DW,
    const int*   __restrict__ uidx_p,
    float* __restrict__ out)
{
    const int bh  = blockIdx.x;           // 0..191  (b*96 + h)
    const int tid = threadIdx.x;          // 0..95

    __shared__ float q_s[S96];
    __shared__ float k_s[S96];
    __shared__ float t_s[S96];

    const int uidx = *uidx_p;
    const float* __restrict__ W = DW + (size_t)uidx * S96 * S96;

    // Q[b,h,3,:] and K[b,h,3,:]  -> offset ((bh)*96 + 3)*96
    const size_t qk_base = ((size_t)bh * S96 + 3) * S96;
    q_s[tid] = Q[qk_base + tid];
    k_s[tid] = K[qk_base + tid];
    __syncthreads();

    // t[i] = sum_k q[k] * V[b,h,k,i]   (thread tid owns column i=tid; coalesced)
    const float* __restrict__ Vb = V + (size_t)bh * S96 * S96;
    float acc = 0.0f;
    #pragma unroll 8
    for (int k = 0; k < S96; ++k)
        acc += q_s[k] * Vb[k * S96 + tid];
    t_s[tid] = acc;
    __syncthreads();

    // u[v] = scale * sum_i t[i] * W3[i,v]   (thread tid owns column v=tid)
    float acc2 = 0.0f;
    #pragma unroll 8
    for (int i = 0; i < S96; ++i)
        acc2 += t_s[i] * W[i * S96 + tid];

    const float scale = 1.0f / sqrtf(96.0f);
    const float u = acc2 * scale;

    // out[bh][q*96 + tid] = k_s[q] * u   (coalesced 384B rows)
    float* __restrict__ O = out + (size_t)bh * (S96 * S96);
    #pragma unroll 8
    for (int q = 0; q < S96; ++q)
        O[q * S96 + tid] = k_s[q] * u;
}

extern "C" void kernel_launch(void* const* d_in, const int* in_sizes, int n_in,
                              void* d_out, int out_size)
{
    const float* Q  = (const float*)d_in[0];
    const float* K  = (const float*)d_in[1];
    const float* V  = (const float*)d_in[2];
    const float* DW = (const float*)d_in[3];
    const int* uidx = (const int*)d_in[4];
    float* out      = (float*)d_out;

    // one block per (b,h) pair: 2*96 = 192 blocks, 96 threads each
    mma73_kernel<<<192, S96>>>(Q, K, V, DW, uidx, out);
}

// round 2
// speedup vs baseline: 1.2279x; 1.2279x over previous
#include <cuda_runtime.h>

// out[bh][q*96+v] = scale * K[bh,3,q] * u[bh][v]
//   u[v] = sum_i t[i] * W3[i,v],  t[i] = sum_k Q[bh,3,k] * V[bh][k,i]
// One block per bh (192 blocks), 96x8 = 768 threads.

#define SD 96
#define NG 8
#define SPAN 12   // 96 / 8

__global__ __launch_bounds__(SD * NG) void mma73_kernel(
    const float* __restrict__ Q,
    const float* __restrict__ K,
    const float* __restrict__ V,
    const float* __restrict__ DW,
    const int*   __restrict__ uidx_p,
    float* __restrict__ out)
{
    const int bh  = blockIdx.x;       // 0..191
    const int col = threadIdx.x;      // 0..95
    const int grp = threadIdx.y;      // 0..7
    const int tid = grp * SD + col;   // 0..767

    __shared__ float q_s[SD];
    __shared__ float k_s[SD];
    __shared__ float t_s[SD];
    __shared__ float u_s[SD];
    __shared__ float part[NG][SD];

    const float* __restrict__ Vb = V + (size_t)bh * SD * SD;
    const float* __restrict__ W  = DW + (size_t)(*uidx_p) * SD * SD;

    // ---- Prefetch V and W rows into registers (no dependency on q/t) ----
    float v_r[SPAN], w_r[SPAN];
    #pragma unroll
    for (int j = 0; j < SPAN; ++j) {
        const int k = grp * SPAN + j;
        v_r[j] = Vb[k * SD + col];
        w_r[j] = W [k * SD + col];
    }

    if (grp == 0) {
        const size_t qk_base = ((size_t)bh * SD + 3) * SD;
        q_s[col] = Q[qk_base + col];
        k_s[col] = K[qk_base + col];
    }
    __syncthreads();

    // ---- Phase 1: t[col] = sum_k q[k] * V[k,col] ----
    {
        float a = 0.0f;
        #pragma unroll
        for (int j = 0; j < SPAN; ++j)
            a += q_s[grp * SPAN + j] * v_r[j];
        part[grp][col] = a;
    }
    __syncthreads();
    if (grp == 0) {
        float s = 0.0f;
        #pragma unroll
        for (int g = 0; g < NG; ++g) s += part[g][col];
        t_s[col] = s;
    }
    __syncthreads();

    // ---- Phase 2: u[col] = scale * sum_i t[i] * W[i,col] ----
    {
        float a = 0.0f;
        #pragma unroll
        for (int j = 0; j < SPAN; ++j)
            a += t_s[grp * SPAN + j] * w_r[j];
        part[grp][col] = a;
    }
    __syncthreads();
    if (grp == 0) {
        float s = 0.0f;
        #pragma unroll
        for (int g = 0; g < NG; ++g) s += part[g][col];
        u_s[col] = s * rsqrtf(96.0f);
    }
    __syncthreads();

    // ---- Phase 3: out[q*96+v] = k_s[q] * u_s[v], float4 stores ----
    // 9216 floats = 2304 float4; 768 threads x 3 each. 24 float4 per row.
    float4* __restrict__ O4 = (float4*)(out + (size_t)bh * SD * SD);
    #pragma unroll
    for (int r = 0; r < 3; ++r) {
        const int p  = tid + r * (SD * NG);  // 0..2303
        const int q  = p / 24;
        const int v  = (p % 24) * 4;
        const float kq = k_s[q];
        O4[p] = make_float4(kq * u_s[v], kq * u_s[v + 1],
                            kq * u_s[v + 2], kq * u_s[v + 3]);
    }
}

extern "C" void kernel_launch(void* const* d_in, const int* in_sizes, int n_in,
                              void* d_out, int out_size)
{
    const float* Q  = (const float*)d_in[0];
    const float* K  = (const float*)d_in[1];
    const float* V  = (const float*)d_in[2];
    const float* DW = (const float*)d_in[3];
    const int* uidx = (const int*)d_in[4];
    float* out      = (float*)d_out;

    dim3 blk(SD, NG);
    mma73_kernel<<<192, blk>>>(Q, K, V, DW, uidx, out);
}